// round 1
// baseline (speedup 1.0000x reference)
#include <cuda_runtime.h>

#define RREL  3
#define EMBD  32
#define HIDD  64
#define NMAX  300000
#define GMAX  30000
#define TROWS 164   // 26 shape + 10 col + 128 pos

// ---------------- scratch (static device memory; no allocs) ----------------
__device__ float g_h1[(size_t)NMAX * HIDD];            // layer1 accumulator / pre-act
__device__ float g_h2[(size_t)NMAX * HIDD];            // layer2 accumulator / pre-act
__device__ float g_xt[(size_t)NMAX * RREL * HIDD];     // relu(h1) @ W2[r], r=0..2
__device__ float g_inv[NMAX * RREL];                   // 1/max(cnt,1) per (node, rel)
__device__ int   g_cnt[NMAX * RREL];
__device__ int   g_gcnt[GMAX];
__device__ float g_ginv[GMAX];
__device__ float g_tabRoot[TROWS * HIDD];              // emb @ root1 (per table row)
__device__ float g_tabRel[RREL * TROWS * HIDD];        // emb @ W1[r]

// ---------------- helpers ----------------
__device__ __forceinline__ void red_add_v4(float* p, float a, float b, float c, float d) {
    asm volatile("red.global.add.v4.f32 [%0], {%1,%2,%3,%4};"
                 :: "l"(p), "f"(a), "f"(b), "f"(c), "f"(d) : "memory");
}
__device__ __forceinline__ void red_add_v2(float* p, float a, float b) {
    asm volatile("red.global.add.v2.f32 [%0], {%1,%2};"
                 :: "l"(p), "f"(a), "f"(b) : "memory");
}

// ---------------- kernels ----------------
__global__ void k_zero(int N, int G) {
    int t = blockIdx.x * blockDim.x + threadIdx.x;
    if (t < N * RREL) g_cnt[t] = 0;
    if (t < G)        g_gcnt[t] = 0;
}

// Precompute lookup tables: tabRoot[row][j] = emb(row) . root1[:,j]
//                            tabRel[r][row][j] = emb(row) . W1[r][:,j]
__global__ void k_tab(const float* __restrict__ se, const float* __restrict__ ce,
                      const float* __restrict__ pe, const float* __restrict__ W1,
                      const float* __restrict__ root1) {
    int t = blockIdx.x * blockDim.x + threadIdx.x;
    if (t >= 4 * TROWS * HIDD) return;
    int j   = t % HIDD;
    int row = (t / HIDD) % TROWS;
    int rel = t / (HIDD * TROWS);  // 0 = root, 1..3 = relations
    const float* emb; int er;
    if (row < 26)      { emb = se; er = row; }
    else if (row < 36) { emb = ce; er = row - 26; }
    else               { emb = pe; er = row - 36; }
    const float* w = (rel == 0) ? (root1 + j) : (W1 + (size_t)(rel - 1) * EMBD * HIDD + j);
    float s = 0.f;
    #pragma unroll
    for (int k = 0; k < EMBD; k++) s += emb[er * EMBD + k] * w[k * HIDD];
    if (rel == 0) g_tabRoot[row * HIDD + j] = s;
    else          g_tabRel[((rel - 1) * TROWS + row) * HIDD + j] = s;
}

__global__ void k_cnt(const int* __restrict__ ei, const int* __restrict__ et, int E) {
    int e = blockIdx.x * blockDim.x + threadIdx.x;
    if (e >= E) return;
    atomicAdd(&g_cnt[ei[E + e] * RREL + et[e]], 1);
}

__global__ void k_gcnt(const int* __restrict__ batch, int N) {
    int i = blockIdx.x * blockDim.x + threadIdx.x;
    if (i >= N) return;
    atomicAdd(&g_gcnt[batch[i]], 1);
}

__global__ void k_inv(int N) {
    int t = blockIdx.x * blockDim.x + threadIdx.x;
    if (t >= N * RREL) return;
    int c = g_cnt[t];
    g_inv[t] = 1.0f / (float)(c > 0 ? c : 1);
}

__global__ void k_outinit(const float* __restrict__ lin_b, float* __restrict__ out, int G) {
    int g = blockIdx.x * blockDim.x + threadIdx.x;
    if (g >= G) return;
    out[2 * g + 0] = lin_b[0];
    out[2 * g + 1] = lin_b[1];
    int c = g_gcnt[g];
    g_ginv[g] = 1.0f / (float)(c > 0 ? c : 1);
}

// h1[i][:] = b1 + tabRoot[sid] + tabRoot[26+cid] + tabRoot[36+pid]
__global__ void k_init1(const int* __restrict__ sid, const int* __restrict__ cid,
                        const int* __restrict__ pid, const float* __restrict__ b1, int N) {
    int t = blockIdx.x * blockDim.x + threadIdx.x;
    if (t >= N * 16) return;
    int i = t >> 4;
    int j = (t & 15) * 4;
    int si = sid[i], ci = cid[i], pi = pid[i];
    float4 a  = *(const float4*)&g_tabRoot[si * HIDD + j];
    float4 b  = *(const float4*)&g_tabRoot[(26 + ci) * HIDD + j];
    float4 c  = *(const float4*)&g_tabRoot[(36 + pi) * HIDD + j];
    float4 bb = *(const float4*)&b1[j];
    float4 o;
    o.x = a.x + b.x + c.x + bb.x; o.y = a.y + b.y + c.y + bb.y;
    o.z = a.z + b.z + c.z + bb.z; o.w = a.w + b.w + c.w + bb.w;
    *(float4*)&g_h1[(size_t)i * HIDD + j] = o;
}

// Layer-1 scatter: half-warp per edge, 4 feats per lane, v4 reduction
__global__ void k_scat1(const int* __restrict__ ei, const int* __restrict__ et,
                        const int* __restrict__ sid, const int* __restrict__ cid,
                        const int* __restrict__ pid, int E) {
    int tid  = blockIdx.x * blockDim.x + threadIdx.x;
    int lane = tid & 31;
    int e    = ((tid >> 5) << 1) + (lane >> 4);
    int l    = lane & 15;
    if (e >= E) return;
    int s = ei[e], d = ei[E + e], t = et[e];
    float w = g_inv[d * RREL + t];
    int si = sid[s], ci = cid[s], pi = pid[s];
    int j = l * 4;
    const float* base = g_tabRel + (size_t)t * TROWS * HIDD;
    float4 a = *(const float4*)&base[si * HIDD + j];
    float4 b = *(const float4*)&base[(26 + ci) * HIDD + j];
    float4 c = *(const float4*)&base[(36 + pi) * HIDD + j];
    red_add_v4(&g_h1[(size_t)d * HIDD + j],
               (a.x + b.x + c.x) * w, (a.y + b.y + c.y) * w,
               (a.z + b.z + c.z) * w, (a.w + b.w + c.w) * w);
}

// C[N x 256] = relu(h1)[N x 64] @ [root2 | W2_0 | W2_1 | W2_2]
// cols 0..63 -> g_h2 (+b2), cols 64..255 -> g_xt
__global__ __launch_bounds__(256) void k_gemm(const float* __restrict__ root2,
                                              const float* __restrict__ W2,
                                              const float* __restrict__ b2, int N) {
    __shared__ float As[64 * 36];    // [node][k], pad 36 keeps 16B alignment
    __shared__ float Bs[32 * 128];   // [k][col]
    int i0   = blockIdx.x * 64;
    int cb   = blockIdx.y;           // col-block: 0 -> cols 0..127, 1 -> 128..255
    int tid  = threadIdx.x;
    int ctid = tid & 31;             // c0 = ctid*4 within 128
    int ntid = tid >> 5;             // n0 = ntid*8
    float acc[8][4];
    #pragma unroll
    for (int n = 0; n < 8; n++)
        #pragma unroll
        for (int c = 0; c < 4; c++) acc[n][c] = 0.f;

    for (int kt = 0; kt < HIDD; kt += 32) {
        __syncthreads();
        for (int idx = tid; idx < 64 * 32; idx += 256) {
            int i = idx >> 5, k = idx & 31;
            int gi = i0 + i;
            float v = 0.f;
            if (gi < N) { v = g_h1[(size_t)gi * HIDD + kt + k]; v = v > 0.f ? v : 0.f; }
            As[i * 36 + k] = v;
        }
        for (int idx = tid; idx < 32 * 128; idx += 256) {
            int c = idx & 127, k = idx >> 7;
            int C = cb * 128 + c;
            int kk = kt + k;
            float w;
            if (C < 64) w = root2[kk * HIDD + C];
            else {
                int r = (C - 64) >> 6, jj = (C - 64) & 63;
                w = W2[((size_t)r * HIDD + kk) * HIDD + jj];
            }
            Bs[k * 128 + c] = w;
        }
        __syncthreads();
        #pragma unroll
        for (int k = 0; k < 32; k += 4) {
            float4 b0 = *(const float4*)&Bs[(k + 0) * 128 + ctid * 4];
            float4 b1v = *(const float4*)&Bs[(k + 1) * 128 + ctid * 4];
            float4 b2v = *(const float4*)&Bs[(k + 2) * 128 + ctid * 4];
            float4 b3v = *(const float4*)&Bs[(k + 3) * 128 + ctid * 4];
            #pragma unroll
            for (int n = 0; n < 8; n++) {
                float4 av = *(const float4*)&As[(ntid * 8 + n) * 36 + k];
                acc[n][0] += av.x * b0.x + av.y * b1v.x + av.z * b2v.x + av.w * b3v.x;
                acc[n][1] += av.x * b0.y + av.y * b1v.y + av.z * b2v.y + av.w * b3v.y;
                acc[n][2] += av.x * b0.z + av.y * b1v.z + av.z * b2v.z + av.w * b3v.z;
                acc[n][3] += av.x * b0.w + av.y * b1v.w + av.z * b2v.w + av.w * b3v.w;
            }
        }
    }
    int C0 = cb * 128 + ctid * 4;
    #pragma unroll
    for (int n = 0; n < 8; n++) {
        int gi = i0 + ntid * 8 + n;
        if (gi >= N) continue;
        float4 o; o.x = acc[n][0]; o.y = acc[n][1]; o.z = acc[n][2]; o.w = acc[n][3];
        if (C0 < 64) {
            o.x += b2[C0]; o.y += b2[C0 + 1]; o.z += b2[C0 + 2]; o.w += b2[C0 + 3];
            *(float4*)&g_h2[(size_t)gi * HIDD + C0] = o;
        } else {
            *(float4*)&g_xt[(size_t)gi * (RREL * HIDD) + (C0 - 64)] = o;
        }
    }
}

// Layer-2 scatter: gather xt[src][rel], scaled v4 reduction into g_h2[dst]
__global__ void k_scat2(const int* __restrict__ ei, const int* __restrict__ et, int E) {
    int tid  = blockIdx.x * blockDim.x + threadIdx.x;
    int lane = tid & 31;
    int e    = ((tid >> 5) << 1) + (lane >> 4);
    int l    = lane & 15;
    if (e >= E) return;
    int s = ei[e], d = ei[E + e], t = et[e];
    float w = g_inv[d * RREL + t];
    int j = l * 4;
    float4 m = *(const float4*)&g_xt[(size_t)s * (RREL * HIDD) + t * HIDD + j];
    red_add_v4(&g_h2[(size_t)d * HIDD + j], m.x * w, m.y * w, m.z * w, m.w * w);
}

// Per-node: relu(h2) @ lin_W, scaled by 1/graph_cnt, v2 reduction into out (pre-seeded with lin_b)
__global__ void k_final(const int* __restrict__ batch, const float* __restrict__ linW,
                        float* __restrict__ out, int N) {
    int tid  = blockIdx.x * blockDim.x + threadIdx.x;
    int lane = tid & 31;
    int i    = tid >> 5;
    if (i >= N) return;
    float v0 = g_h2[(size_t)i * HIDD + lane];      v0 = v0 > 0.f ? v0 : 0.f;
    float v1 = g_h2[(size_t)i * HIDD + 32 + lane]; v1 = v1 > 0.f ? v1 : 0.f;
    float o0 = v0 * linW[lane * 2]     + v1 * linW[(lane + 32) * 2];
    float o1 = v0 * linW[lane * 2 + 1] + v1 * linW[(lane + 32) * 2 + 1];
    #pragma unroll
    for (int off = 16; off > 0; off >>= 1) {
        o0 += __shfl_down_sync(0xffffffffu, o0, off);
        o1 += __shfl_down_sync(0xffffffffu, o1, off);
    }
    if (lane == 0) {
        int b = batch[i];
        float w = g_ginv[b];
        red_add_v2(&out[2 * b], o0 * w, o1 * w);
    }
}

// ---------------- launch ----------------
extern "C" void kernel_launch(void* const* d_in, const int* in_sizes, int n_in,
                              void* d_out, int out_size) {
    const int* sid = (const int*)d_in[0];
    const int* cid = (const int*)d_in[1];
    const int* pid = (const int*)d_in[2];
    const int* ei  = (const int*)d_in[3];
    const int* et  = (const int*)d_in[4];
    const int* bat = (const int*)d_in[5];
    // num_graphs may or may not be materialized as a device scalar
    int off = (in_sizes[6] == 1) ? 7 : 6;
    const float* se    = (const float*)d_in[off + 0];
    const float* ce    = (const float*)d_in[off + 1];
    const float* pe    = (const float*)d_in[off + 2];
    const float* W1    = (const float*)d_in[off + 3];
    const float* root1 = (const float*)d_in[off + 4];
    const float* b1    = (const float*)d_in[off + 5];
    const float* W2    = (const float*)d_in[off + 6];
    const float* root2 = (const float*)d_in[off + 7];
    const float* b2    = (const float*)d_in[off + 8];
    const float* linW  = (const float*)d_in[off + 9];
    const float* linb  = (const float*)d_in[off + 10];
    float* out = (float*)d_out;

    int N = in_sizes[0];
    int E = in_sizes[4];
    int G = out_size / 2;
    const int TB = 256;

    k_zero<<<(N * RREL + TB - 1) / TB, TB>>>(N, G);
    k_tab<<<(4 * TROWS * HIDD + TB - 1) / TB, TB>>>(se, ce, pe, W1, root1);
    k_cnt<<<(E + TB - 1) / TB, TB>>>(ei, et, E);
    k_gcnt<<<(N + TB - 1) / TB, TB>>>(bat, N);
    k_inv<<<(N * RREL + TB - 1) / TB, TB>>>(N);
    k_outinit<<<(G + TB - 1) / TB, TB>>>(linb, out, G);
    k_init1<<<(N * 16 + TB - 1) / TB, TB>>>(sid, cid, pid, b1, N);
    {
        long long thr = ((long long)(E + 1) / 2) * 32;
        k_scat1<<<(int)((thr + TB - 1) / TB), TB>>>(ei, et, sid, cid, pid, E);
    }
    {
        dim3 grid((N + 63) / 64, 2);
        k_gemm<<<grid, TB>>>(root2, W2, b2, N);
    }
    {
        long long thr = ((long long)(E + 1) / 2) * 32;
        k_scat2<<<(int)((thr + TB - 1) / TB), TB>>>(ei, et, E);
    }
    k_final<<<(N * 32 + TB - 1) / TB, TB>>>(bat, linW, out, N);
}

// round 3
// speedup vs baseline: 1.1431x; 1.1431x over previous
#include <cuda_runtime.h>

#define RREL  3
#define EMBD  32
#define HIDD  64
#define NMAX  300000
#define EMAX  1500000
#define GMAX  30000
#define TROWS 164   // 26 shape + 10 col + 128 pos

// ---------------- scratch (static device memory; no allocs) ----------------
__device__ float g_h1[(size_t)NMAX * HIDD];            // relu(layer1 out)
__device__ float g_h2[(size_t)NMAX * HIDD];            // layer2 pre-act
__device__ float g_agg[(size_t)NMAX * RREL * HIDD];    // per-rel aggregated relu(h1)
__device__ float g_inv[NMAX * RREL];                   // 1/max(cnt,1) per (node, rel)
__device__ int   g_cnt[NMAX * RREL];
__device__ int   g_base[NMAX];                         // CSR row start
__device__ int   g_fill[NMAX];                         // CSR fill cursor (== deg after place)
__device__ int   g_gcnt[GMAX];
__device__ float g_ginv[GMAX];
__device__ int   g_ctr[1];
__device__ unsigned int g_epack[EMAX];                 // src | rel<<20, grouped by dst
__device__ unsigned int g_epack2[EMAX];                // si | ci<<5 | pi<<9 | rel<<16
__device__ float g_tabRoot[TROWS * HIDD];              // emb-row @ root1
__device__ float g_tabRel[RREL * TROWS * HIDD];        // emb-row @ W1[r]

__device__ __forceinline__ void red_add_v2(float* p, float a, float b) {
    asm volatile("red.global.add.v2.f32 [%0], {%1,%2};"
                 :: "l"(p), "f"(a), "f"(b) : "memory");
}

// ---------------- kernels ----------------
__global__ void k_zero(int N, int G) {
    int t = blockIdx.x * blockDim.x + threadIdx.x;
    if (t < N * RREL) g_cnt[t] = 0;
    if (t < N)        g_fill[t] = 0;
    if (t < G)        g_gcnt[t] = 0;
    if (t == 0)       g_ctr[0] = 0;
}

// tabRoot[row][j] = emb(row) . root1[:,j] ; tabRel[r][row][j] = emb(row) . W1[r][:,j]
__global__ void k_tab(const float* __restrict__ se, const float* __restrict__ ce,
                      const float* __restrict__ pe, const float* __restrict__ W1,
                      const float* __restrict__ root1) {
    int t = blockIdx.x * blockDim.x + threadIdx.x;
    if (t >= 4 * TROWS * HIDD) return;
    int j   = t % HIDD;
    int row = (t / HIDD) % TROWS;
    int rel = t / (HIDD * TROWS);  // 0 = root, 1..3 = relations
    const float* emb; int er;
    if (row < 26)      { emb = se; er = row; }
    else if (row < 36) { emb = ce; er = row - 26; }
    else               { emb = pe; er = row - 36; }
    const float* w = (rel == 0) ? (root1 + j) : (W1 + (size_t)(rel - 1) * EMBD * HIDD + j);
    float s = 0.f;
    #pragma unroll
    for (int k = 0; k < EMBD; k++) s += emb[er * EMBD + k] * w[k * HIDD];
    if (rel == 0) g_tabRoot[row * HIDD + j] = s;
    else          g_tabRel[((rel - 1) * TROWS + row) * HIDD + j] = s;
}

__global__ void k_cnt(const int* __restrict__ ei, const int* __restrict__ et, int E) {
    int e = blockIdx.x * blockDim.x + threadIdx.x;
    if (e >= E) return;
    atomicAdd(&g_cnt[ei[E + e] * RREL + et[e]], 1);
}

// Per node: inv weights, graph counts, and CSR base via warp-aggregated atomic.
__global__ void k_base(const int* __restrict__ batch, int N) {
    int t    = blockIdx.x * blockDim.x + threadIdx.x;
    int lane = threadIdx.x & 31;
    int deg  = 0;
    if (t < N) {
        int c0 = g_cnt[3 * t], c1 = g_cnt[3 * t + 1], c2 = g_cnt[3 * t + 2];
        deg = c0 + c1 + c2;
        g_inv[3 * t + 0] = 1.0f / (float)(c0 > 0 ? c0 : 1);
        g_inv[3 * t + 1] = 1.0f / (float)(c1 > 0 ? c1 : 1);
        g_inv[3 * t + 2] = 1.0f / (float)(c2 > 0 ? c2 : 1);
        atomicAdd(&g_gcnt[batch[t]], 1);
    }
    int incl = deg;
    #pragma unroll
    for (int off = 1; off < 32; off <<= 1) {
        int v = __shfl_up_sync(0xffffffffu, incl, off);
        if (lane >= off) incl += v;
    }
    int total = __shfl_sync(0xffffffffu, incl, 31);
    int base = 0;
    if (lane == 31 && total > 0) base = atomicAdd(&g_ctr[0], total);
    base = __shfl_sync(0xffffffffu, base, 31);
    if (t < N) g_base[t] = base + incl - deg;
}

__global__ void k_place(const int* __restrict__ ei, const int* __restrict__ et,
                        const int* __restrict__ sid, const int* __restrict__ cid,
                        const int* __restrict__ pid, int E) {
    int e = blockIdx.x * blockDim.x + threadIdx.x;
    if (e >= E) return;
    int s = ei[e], d = ei[E + e], r = et[e];
    int pos = g_base[d] + atomicAdd(&g_fill[d], 1);
    g_epack[pos]  = (unsigned)s | ((unsigned)r << 20);
    g_epack2[pos] = (unsigned)sid[s] | ((unsigned)cid[s] << 5)
                  | ((unsigned)pid[s] << 9) | ((unsigned)r << 16);
}

// Layer 1: warp per dst node, lane covers 2 feature cols; stores relu(h1).
__global__ void k_agg1(const int* __restrict__ sid, const int* __restrict__ cid,
                       const int* __restrict__ pid, const float* __restrict__ b1, int N) {
    int lane = threadIdx.x & 31;
    int d = blockIdx.x * (blockDim.x >> 5) + (threadIdx.x >> 5);
    if (d >= N) return;
    int j  = lane * 2;
    int e0 = g_base[d], e1 = e0 + g_fill[d];
    float2 acc = {0.f, 0.f};
    for (int e = e0; e < e1; e++) {
        unsigned p = g_epack2[e];
        int si  = p & 31;
        int ci  = (p >> 5) & 15;
        int pi  = (p >> 9) & 127;
        int rel = (int)(p >> 16);
        float w = g_inv[3 * d + rel];
        const float* tb = g_tabRel + (size_t)rel * (TROWS * HIDD);
        float2 m0 = *(const float2*)&tb[si * HIDD + j];
        float2 m1 = *(const float2*)&tb[(26 + ci) * HIDD + j];
        float2 m2 = *(const float2*)&tb[(36 + pi) * HIDD + j];
        acc.x += w * (m0.x + m1.x + m2.x);
        acc.y += w * (m0.y + m1.y + m2.y);
    }
    int si = sid[d], ci = cid[d], pi = pid[d];
    float2 r0 = *(const float2*)&g_tabRoot[si * HIDD + j];
    float2 r1 = *(const float2*)&g_tabRoot[(26 + ci) * HIDD + j];
    float2 r2 = *(const float2*)&g_tabRoot[(36 + pi) * HIDD + j];
    float2 bv = *(const float2*)&b1[j];
    float hx = acc.x + r0.x + r1.x + r2.x + bv.x;
    float hy = acc.y + r0.y + r1.y + r2.y + bv.y;
    float2 o;
    o.x = hx > 0.f ? hx : 0.f;
    o.y = hy > 0.f ? hy : 0.f;
    *(float2*)&g_h1[(size_t)d * HIDD + j] = o;
}

__global__ void k_outinit(const float* __restrict__ lin_b, float* __restrict__ out, int G) {
    int g = blockIdx.x * blockDim.x + threadIdx.x;
    if (g >= G) return;
    out[2 * g + 0] = lin_b[0];
    out[2 * g + 1] = lin_b[1];
    int c = g_gcnt[g];
    g_ginv[g] = 1.0f / (float)(c > 0 ? c : 1);
}

// Layer 2 feature aggregation (pre-transform): agg[d][r][:] = sum_{e in N_r(d)} w * h1[src]
__global__ void k_agg2(int N) {
    int lane = threadIdx.x & 31;
    int d = blockIdx.x * (blockDim.x >> 5) + (threadIdx.x >> 5);
    if (d >= N) return;
    int j  = lane * 2;
    int e0 = g_base[d], e1 = e0 + g_fill[d];
    float2 a0 = {0.f, 0.f}, a1 = {0.f, 0.f}, a2 = {0.f, 0.f};
    for (int e = e0; e < e1; e++) {
        unsigned p = g_epack[e];
        int src = p & 0xFFFFF, rel = (int)(p >> 20);
        float w = g_inv[3 * d + rel];
        float2 v = *(const float2*)&g_h1[(size_t)src * HIDD + j];
        float vx = v.x * w, vy = v.y * w;
        if (rel == 0)      { a0.x += vx; a0.y += vy; }
        else if (rel == 1) { a1.x += vx; a1.y += vy; }
        else               { a2.x += vx; a2.y += vy; }
    }
    float* dst = g_agg + (size_t)d * (RREL * HIDD);
    *(float2*)&dst[j]       = a0;
    *(float2*)&dst[64 + j]  = a1;
    *(float2*)&dst[128 + j] = a2;
}

// h2[N x 64] = [relu(h1) | agg] (N x 256) @ [root2; W2_0; W2_1; W2_2] (256 x 64) + b2
// f32x2 packed FMA; block = 128 nodes x 64 cols, 256 threads.
#define ASP 132  // 128 + 4 pad
#define BSP 68   // 64 + 4 pad
__global__ __launch_bounds__(256) void k_gemm(const float* __restrict__ root2,
                                              const float* __restrict__ W2,
                                              const float* __restrict__ b2, int N) {
    __shared__ float As[32 * ASP];   // [k][node]
    __shared__ float Bs[32 * BSP];   // [k][col]
    int i0  = blockIdx.x * 128;
    int tid = threadIdx.x;
    int cg  = tid & 15;   // col group: cols cg*4 .. cg*4+3
    int ng  = tid >> 4;   // node group: nodes ng*8 .. ng*8+7
    unsigned long long acc[16];
    #pragma unroll
    for (int i = 0; i < 16; i++) acc[i] = 0ull;

    for (int kt = 0; kt < 256; kt += 32) {
        __syncthreads();
        // load B chunk [32 x 64]
        #pragma unroll
        for (int t = 0; t < 8; t++) {
            int idx = tid + t * 256;
            int c = idx & 63, k = idx >> 6;
            int kk = kt + k;
            float w;
            if (kk < 64) w = root2[kk * HIDD + c];
            else {
                int r = (kk - 64) >> 6, kr = (kk - 64) & 63;
                w = W2[((size_t)r * HIDD + kr) * HIDD + c];
            }
            Bs[k * BSP + c] = w;
        }
        // load A chunk [128 nodes x 32 k], store transposed
        #pragma unroll
        for (int t = 0; t < 4; t++) {
            int idx = tid + t * 256;
            int node = idx & 127, kq = idx >> 7;  // kq 0..7
            int k0 = kq * 4;
            int gi = i0 + node;
            float4 v = {0.f, 0.f, 0.f, 0.f};
            if (gi < N) {
                int kk = kt + k0;
                if (kk < 64) v = *(const float4*)&g_h1[(size_t)gi * HIDD + kk];
                else         v = *(const float4*)&g_agg[(size_t)gi * (RREL * HIDD) + (kk - 64)];
            }
            As[(k0 + 0) * ASP + node] = v.x;
            As[(k0 + 1) * ASP + node] = v.y;
            As[(k0 + 2) * ASP + node] = v.z;
            As[(k0 + 3) * ASP + node] = v.w;
        }
        __syncthreads();
        #pragma unroll
        for (int k = 0; k < 32; k++) {
            float4 bv = *(const float4*)&Bs[k * BSP + cg * 4];
            unsigned long long pb0, pb1;
            asm("mov.b64 %0, {%1, %2};" : "=l"(pb0) : "f"(bv.x), "f"(bv.y));
            asm("mov.b64 %0, {%1, %2};" : "=l"(pb1) : "f"(bv.z), "f"(bv.w));
            float4 a0 = *(const float4*)&As[k * ASP + ng * 8];
            float4 a1 = *(const float4*)&As[k * ASP + ng * 8 + 4];
            float av[8] = {a0.x, a0.y, a0.z, a0.w, a1.x, a1.y, a1.z, a1.w};
            #pragma unroll
            for (int n = 0; n < 8; n++) {
                unsigned long long pa;
                asm("mov.b64 %0, {%1, %1};" : "=l"(pa) : "f"(av[n]));
                asm("fma.rn.f32x2 %0, %1, %2, %0;" : "+l"(acc[2 * n])     : "l"(pa), "l"(pb0));
                asm("fma.rn.f32x2 %0, %1, %2, %0;" : "+l"(acc[2 * n + 1]) : "l"(pa), "l"(pb1));
            }
        }
    }
    float4 b2v = *(const float4*)&b2[cg * 4];
    #pragma unroll
    for (int n = 0; n < 8; n++) {
        int gi = i0 + ng * 8 + n;
        if (gi >= N) continue;
        float x0, x1, x2, x3;
        asm("mov.b64 {%0, %1}, %2;" : "=f"(x0), "=f"(x1) : "l"(acc[2 * n]));
        asm("mov.b64 {%0, %1}, %2;" : "=f"(x2), "=f"(x3) : "l"(acc[2 * n + 1]));
        float4 o;
        o.x = x0 + b2v.x; o.y = x1 + b2v.y; o.z = x2 + b2v.z; o.w = x3 + b2v.w;
        *(float4*)&g_h2[(size_t)gi * HIDD + cg * 4] = o;
    }
}

// Per-node: relu(h2) @ lin_W, scaled by 1/graph_cnt, v2 reduction into out (seeded with lin_b)
__global__ void k_final(const int* __restrict__ batch, const float* __restrict__ linW,
                        float* __restrict__ out, int N) {
    int tid  = blockIdx.x * blockDim.x + threadIdx.x;
    int lane = tid & 31;
    int i    = tid >> 5;
    if (i >= N) return;
    float v0 = g_h2[(size_t)i * HIDD + lane];      v0 = v0 > 0.f ? v0 : 0.f;
    float v1 = g_h2[(size_t)i * HIDD + 32 + lane]; v1 = v1 > 0.f ? v1 : 0.f;
    float o0 = v0 * linW[lane * 2]     + v1 * linW[(lane + 32) * 2];
    float o1 = v0 * linW[lane * 2 + 1] + v1 * linW[(lane + 32) * 2 + 1];
    #pragma unroll
    for (int off = 16; off > 0; off >>= 1) {
        o0 += __shfl_down_sync(0xffffffffu, o0, off);
        o1 += __shfl_down_sync(0xffffffffu, o1, off);
    }
    if (lane == 0) {
        int b = batch[i];
        float w = g_ginv[b];
        red_add_v2(&out[2 * b], o0 * w, o1 * w);
    }
}

// ---------------- launch ----------------
extern "C" void kernel_launch(void* const* d_in, const int* in_sizes, int n_in,
                              void* d_out, int out_size) {
    const int* sid = (const int*)d_in[0];
    const int* cid = (const int*)d_in[1];
    const int* pid = (const int*)d_in[2];
    const int* ei  = (const int*)d_in[3];
    const int* et  = (const int*)d_in[4];
    const int* bat = (const int*)d_in[5];
    int off = (in_sizes[6] == 1) ? 7 : 6;
    const float* se    = (const float*)d_in[off + 0];
    const float* ce    = (const float*)d_in[off + 1];
    const float* pe    = (const float*)d_in[off + 2];
    const float* W1    = (const float*)d_in[off + 3];
    const float* root1 = (const float*)d_in[off + 4];
    const float* b1    = (const float*)d_in[off + 5];
    const float* W2    = (const float*)d_in[off + 6];
    const float* root2 = (const float*)d_in[off + 7];
    const float* b2    = (const float*)d_in[off + 8];
    const float* linW  = (const float*)d_in[off + 9];
    const float* linb  = (const float*)d_in[off + 10];
    float* out = (float*)d_out;

    int N = in_sizes[0];
    int E = in_sizes[4];
    int G = out_size / 2;
    const int TB = 256;

    k_zero<<<(N * RREL + TB - 1) / TB, TB>>>(N, G);
    k_tab<<<(4 * TROWS * HIDD + TB - 1) / TB, TB>>>(se, ce, pe, W1, root1);
    k_cnt<<<(E + TB - 1) / TB, TB>>>(ei, et, E);
    k_base<<<(N + TB - 1) / TB, TB>>>(bat, N);
    k_place<<<(E + TB - 1) / TB, TB>>>(ei, et, sid, cid, pid, E);
    k_agg1<<<(N * 32 + TB - 1) / TB, TB>>>(sid, cid, pid, b1, N);
    k_outinit<<<(G + TB - 1) / TB, TB>>>(linb, out, G);
    k_agg2<<<(N * 32 + TB - 1) / TB, TB>>>(N);
    k_gemm<<<(N + 127) / 128, TB>>>(root2, W2, b2, N);
    k_final<<<(N * 32 + TB - 1) / TB, TB>>>(bat, linW, out, N);
}